// round 2
// baseline (speedup 1.0000x reference)
#include <cuda_runtime.h>
#include <cstdint>

#define NNODES 50000
#define NEDGES 800000
#define FDIM   128          // embedding / output width
#define HDIM2  256          // hidden width after W1

// ---------------- scratch (static __device__, no allocations) ----------------
__device__ __align__(16) float g_scat0[(size_t)NNODES * FDIM];   // A * E[x]
__device__ __align__(16) float g_h1[(size_t)NNODES * HDIM2];     // relu(scat0@W1+b1)
__device__ __align__(16) float g_t[(size_t)NNODES * FDIM];       // h1 @ W2
__device__ __align__(16) float g_deg[NNODES];
__device__ __align__(16) float g_invs[NNODES];
__device__ __align__(16) float g_norm[NEDGES];
__device__ int g_src[NEDGES];
__device__ int g_dst[NEDGES];
__device__ int g_xi[NNODES];
__device__ int g_is64;

// ---------------- helpers ----------------
__device__ __forceinline__ void red_add_v4(float* ptr, float4 v) {
    asm volatile("red.global.add.v4.f32 [%0], {%1,%2,%3,%4};"
                 :: "l"(ptr), "f"(v.x), "f"(v.y), "f"(v.z), "f"(v.w)
                 : "memory");
}

// ---------------- zero scratch + out + deg + flag ----------------
__global__ void zero_all_kernel(float4* __restrict__ out4) {
    int i = blockIdx.x * blockDim.x + threadIdx.x;
    const int n4 = NNODES * FDIM / 4;                        // 1,600,000
    if (i < n4) {
        reinterpret_cast<float4*>(g_scat0)[i] = make_float4(0.f, 0.f, 0.f, 0.f);
        out4[i] = make_float4(0.f, 0.f, 0.f, 0.f);
    }
    if (i < NNODES) g_deg[i] = 0.f;
    if (i == 0) g_is64 = 1;
}

// ---------------- dtype detection ----------------
// If the edge buffer is int64 (values < 2^31, nonneg), every odd 32-bit word
// is zero. If int32, odd words are edge endpoint values (~never all zero
// across 2048 samples of random ids in [0, 50000)).
__global__ void detect_kernel(const unsigned int* __restrict__ w) {
    int i = threadIdx.x;                   // 1024 threads
    unsigned v = w[2 * i + 1] | w[2 * (i + 1024) + 1];
    if (v) g_is64 = 0;
}

// ---------------- convert indices to int32 ----------------
__global__ void convert_kernel(const void* __restrict__ ei,
                               const void* __restrict__ x) {
    int e = blockIdx.x * blockDim.x + threadIdx.x;
    int is64 = g_is64;
    if (e < NEDGES) {
        if (is64) {
            g_src[e] = (int)((const long long*)ei)[e];
            g_dst[e] = (int)((const long long*)ei)[NEDGES + e];
        } else {
            g_src[e] = ((const int*)ei)[e];
            g_dst[e] = ((const int*)ei)[NEDGES + e];
        }
    }
    if (e < NNODES) {
        g_xi[e] = is64 ? (int)((const long long*)x)[e] : ((const int*)x)[e];
    }
}

// ---------------- degree count ----------------
__global__ void deg_kernel() {
    int e = blockIdx.x * blockDim.x + threadIdx.x;
    if (e >= NEDGES) return;
    atomicAdd(&g_deg[g_dst[e]], 1.0f);
}

__global__ void invs_kernel() {
    int i = blockIdx.x * blockDim.x + threadIdx.x;
    if (i >= NNODES) return;
    g_invs[i] = rsqrtf(g_deg[i] + 1.0f);   // +1 = self loop
}

__global__ void norm_kernel() {
    int e = blockIdx.x * blockDim.x + threadIdx.x;
    if (e >= NEDGES) return;
    g_norm[e] = g_invs[g_src[e]] * g_invs[g_dst[e]];
}

// ---------------- scatter layer 1: g_scat0[dst] += norm * emb[x[src]] --------
__global__ void scatter1_kernel(const float* __restrict__ emb) {
    int gw = (blockIdx.x * blockDim.x + threadIdx.x) >> 5;
    int lane = threadIdx.x & 31;
    if (gw >= NEDGES) return;
    int s = g_src[gw];
    int d = g_dst[gw];
    float norm = g_norm[gw];
    int xs = g_xi[s];
    float4 v = *reinterpret_cast<const float4*>(emb + (size_t)xs * FDIM + lane * 4);
    v.x *= norm; v.y *= norm; v.z *= norm; v.w *= norm;
    red_add_v4(g_scat0 + (size_t)d * FDIM + lane * 4, v);
}

// ---------------- self loop for layer 1 ----------------
__global__ void self1_kernel(const float* __restrict__ emb) {
    int gw = (blockIdx.x * blockDim.x + threadIdx.x) >> 5;
    int lane = threadIdx.x & 31;
    if (gw >= NNODES) return;
    float iv = g_invs[gw];
    float nrm = iv * iv;
    int xs = g_xi[gw];
    float4 e = *reinterpret_cast<const float4*>(emb + (size_t)xs * FDIM + lane * 4);
    float4* p = reinterpret_cast<float4*>(g_scat0 + (size_t)gw * FDIM + lane * 4);
    float4 c = *p;
    c.x += nrm * e.x; c.y += nrm * e.y; c.z += nrm * e.z; c.w += nrm * e.w;
    *p = c;
}

// ---------------- SGEMM: C[M,N] = A[M,K] @ B[K,N] (+bias)(relu) --------------
#define BM 64
#define BN 128
#define BK 32
__global__ __launch_bounds__(256)
void sgemm_kernel(const float* __restrict__ A, const float* __restrict__ B,
                  const float* __restrict__ bias, float* __restrict__ C,
                  int M, int N, int K, int do_relu) {
    __shared__ float As[BM][BK + 1];
    __shared__ float Bs[BK][BN];

    int tid = threadIdx.x;
    int row0 = blockIdx.y * BM;
    int col0 = blockIdx.x * BN;
    int trow = tid >> 4;   // 0..15 -> 4 rows each
    int tcol = tid & 15;   // 0..15 -> 8 cols each

    float acc[4][8];
#pragma unroll
    for (int r = 0; r < 4; r++)
#pragma unroll
        for (int c = 0; c < 8; c++) acc[r][c] = 0.f;

    for (int k0 = 0; k0 < K; k0 += BK) {
        for (int i = tid; i < BM * (BK / 4); i += 256) {
            int r = i / (BK / 4);
            int c4 = i % (BK / 4);
            int gr = row0 + r;
            float4 v = make_float4(0.f, 0.f, 0.f, 0.f);
            if (gr < M)
                v = *reinterpret_cast<const float4*>(A + (size_t)gr * K + k0 + c4 * 4);
            As[r][c4 * 4 + 0] = v.x;
            As[r][c4 * 4 + 1] = v.y;
            As[r][c4 * 4 + 2] = v.z;
            As[r][c4 * 4 + 3] = v.w;
        }
        for (int i = tid; i < BK * (BN / 4); i += 256) {
            int r = i / (BN / 4);
            int c4 = i % (BN / 4);
            *reinterpret_cast<float4*>(&Bs[r][c4 * 4]) =
                *reinterpret_cast<const float4*>(B + (size_t)(k0 + r) * N + col0 + c4 * 4);
        }
        __syncthreads();

#pragma unroll
        for (int k = 0; k < BK; k++) {
            float a[4];
#pragma unroll
            for (int r = 0; r < 4; r++) a[r] = As[trow * 4 + r][k];
            float4 b0 = *reinterpret_cast<float4*>(&Bs[k][tcol * 8]);
            float4 b1 = *reinterpret_cast<float4*>(&Bs[k][tcol * 8 + 4]);
#pragma unroll
            for (int r = 0; r < 4; r++) {
                acc[r][0] += a[r] * b0.x;
                acc[r][1] += a[r] * b0.y;
                acc[r][2] += a[r] * b0.z;
                acc[r][3] += a[r] * b0.w;
                acc[r][4] += a[r] * b1.x;
                acc[r][5] += a[r] * b1.y;
                acc[r][6] += a[r] * b1.z;
                acc[r][7] += a[r] * b1.w;
            }
        }
        __syncthreads();
    }

    float bv[8];
#pragma unroll
    for (int c = 0; c < 8; c++)
        bv[c] = bias ? bias[col0 + tcol * 8 + c] : 0.f;

#pragma unroll
    for (int r = 0; r < 4; r++) {
        int gr = row0 + trow * 4 + r;
        if (gr >= M) continue;
        float4 o0, o1;
        o0.x = acc[r][0] + bv[0]; o0.y = acc[r][1] + bv[1];
        o0.z = acc[r][2] + bv[2]; o0.w = acc[r][3] + bv[3];
        o1.x = acc[r][4] + bv[4]; o1.y = acc[r][5] + bv[5];
        o1.z = acc[r][6] + bv[6]; o1.w = acc[r][7] + bv[7];
        if (do_relu) {
            o0.x = fmaxf(o0.x, 0.f); o0.y = fmaxf(o0.y, 0.f);
            o0.z = fmaxf(o0.z, 0.f); o0.w = fmaxf(o0.w, 0.f);
            o1.x = fmaxf(o1.x, 0.f); o1.y = fmaxf(o1.y, 0.f);
            o1.z = fmaxf(o1.z, 0.f); o1.w = fmaxf(o1.w, 0.f);
        }
        *reinterpret_cast<float4*>(C + (size_t)gr * N + col0 + tcol * 8) = o0;
        *reinterpret_cast<float4*>(C + (size_t)gr * N + col0 + tcol * 8 + 4) = o1;
    }
}

// ---------------- scatter layer 2: out[dst] += norm * t[src] -----------------
__global__ void scatter2_kernel(float* __restrict__ out) {
    int gw = (blockIdx.x * blockDim.x + threadIdx.x) >> 5;
    int lane = threadIdx.x & 31;
    if (gw >= NEDGES) return;
    int s = g_src[gw];
    int d = g_dst[gw];
    float norm = g_norm[gw];
    float4 v = *reinterpret_cast<const float4*>(g_t + (size_t)s * FDIM + lane * 4);
    v.x *= norm; v.y *= norm; v.z *= norm; v.w *= norm;
    red_add_v4(out + (size_t)d * FDIM + lane * 4, v);
}

// ---------------- final: out += invs^2 * t + b2 ------------------------------
__global__ void final_kernel(const float* __restrict__ b2,
                             float* __restrict__ out) {
    int gw = (blockIdx.x * blockDim.x + threadIdx.x) >> 5;
    int lane = threadIdx.x & 31;
    if (gw >= NNODES) return;
    float iv = g_invs[gw];
    float nrm = iv * iv;
    float4 t = *reinterpret_cast<const float4*>(g_t + (size_t)gw * FDIM + lane * 4);
    float4 b = *reinterpret_cast<const float4*>(b2 + lane * 4);
    float4* p = reinterpret_cast<float4*>(out + (size_t)gw * FDIM + lane * 4);
    float4 c = *p;
    c.x += nrm * t.x + b.x;
    c.y += nrm * t.y + b.y;
    c.z += nrm * t.z + b.z;
    c.w += nrm * t.w + b.w;
    *p = c;
}

// ---------------- launch ----------------
extern "C" void kernel_launch(void* const* d_in, const int* in_sizes, int n_in,
                              void* d_out, int out_size) {
    const void*  x   = d_in[0];                 // (50000,1) int32 or int64
    const void*  ei  = d_in[1];                 // (2,800000) int32 or int64
    const float* emb = (const float*)d_in[2];   // 4096x128
    const float* W1  = (const float*)d_in[3];   // 128x256
    const float* b1  = (const float*)d_in[4];   // 256
    const float* W2  = (const float*)d_in[5];   // 256x128
    const float* b2  = (const float*)d_in[6];   // 128
    float* out = (float*)d_out;                 // 50000x128

    float* scat0p; cudaGetSymbolAddress((void**)&scat0p, g_scat0);
    float* h1p;    cudaGetSymbolAddress((void**)&h1p, g_h1);
    float* tp;     cudaGetSymbolAddress((void**)&tp, g_t);

    // 1) zero scratch + output + deg + flag
    {
        int n4 = NNODES * FDIM / 4;
        zero_all_kernel<<<(n4 + 255) / 256, 256>>>((float4*)out);
    }
    // 2) dtype detect + index conversion
    detect_kernel<<<1, 1024>>>((const unsigned int*)ei);
    convert_kernel<<<(NEDGES + 255) / 256, 256>>>(ei, x);
    // 3) degrees + norms
    deg_kernel<<<(NEDGES + 255) / 256, 256>>>();
    invs_kernel<<<(NNODES + 255) / 256, 256>>>();
    norm_kernel<<<(NEDGES + 255) / 256, 256>>>();
    // 4) scatter1 (warp per edge)
    scatter1_kernel<<<(NEDGES * 32) / 256, 256>>>(emb);
    // 5) self loop layer 1
    self1_kernel<<<(NNODES * 32 + 255) / 256, 256>>>(emb);
    // 6) GEMM1: h1 = relu(scat0 @ W1 + b1)   [50000x128 @ 128x256]
    {
        dim3 grid(HDIM2 / BN, (NNODES + BM - 1) / BM);
        sgemm_kernel<<<grid, 256>>>(scat0p, W1, b1, h1p, NNODES, HDIM2, FDIM, 1);
    }
    // 7) GEMM2: t = h1 @ W2                  [50000x256 @ 256x128]
    {
        dim3 grid(FDIM / BN, (NNODES + BM - 1) / BM);
        sgemm_kernel<<<grid, 256>>>(h1p, W2, nullptr, tp, NNODES, FDIM, HDIM2, 0);
    }
    // 8) scatter2
    scatter2_kernel<<<(NEDGES * 32) / 256, 256>>>(out);
    // 9) self loop + bias
    final_kernel<<<(NNODES * 32 + 255) / 256, 256>>>(b2, out);
}